// round 7
// baseline (speedup 1.0000x reference)
#include <cuda_runtime.h>
#include <math.h>

#define NN 65536
#define EE 1048576
#define CC 101
#define BNEPS 1e-5f

// ---------------- device scratch (no allocations allowed) ----------------
__device__ float  g_z[NN * 128];      // z = concat[x,pos] @ Wl   (up to 2 fused convs)
__device__ float  g_m[NN * 128];      // agg = segmax(z) - pos@Wl_pos
__device__ float  g_h1[NN * 64];      // pre-BN conv outputs
__device__ float  g_h2[NN * 64];
__device__ float  g_h3[NN * 64];
__device__ int    g_deg[NN];
__device__ int    g_rowptr[NN + 1];
__device__ int    g_cursor[NN];
__device__ int    g_col[EE];
__device__ int    g_bsum[256];
__device__ double g_sum[192];
__device__ double g_sumsq[192];
__device__ float  g_s[192];           // BN scale  (fold into next-stage load)
__device__ float  g_t[192];           // BN shift

// ---------------- f32x2 helpers (Blackwell packed fp32) ----------------
typedef unsigned long long u64;
__device__ __forceinline__ u64 pk2(float x, float y) {
    u64 r; asm("mov.b64 %0,{%1,%2};" : "=l"(r) : "f"(x), "f"(y)); return r;
}
__device__ __forceinline__ void upk2(u64 v, float& x, float& y) {
    asm("mov.b64 {%0,%1},%2;" : "=f"(x), "=f"(y) : "l"(v));
}
__device__ __forceinline__ u64 f2fma(u64 a, u64 b, u64 c) {
    u64 d; asm("fma.rn.f32x2 %0,%1,%2,%3;" : "=l"(d) : "l"(a), "l"(b), "l"(c)); return d;
}
__device__ __forceinline__ u64 f2add(u64 a, u64 b) {
    u64 d; asm("add.rn.f32x2 %0,%1,%2;" : "=l"(d) : "l"(a), "l"(b)); return d;
}

// ---------------- CSR build ----------------
__global__ void zero_kernel() {
    int i = blockIdx.x * blockDim.x + threadIdx.x;
    if (i < NN) g_deg[i] = 0;
    if (i < 192) { g_sum[i] = 0.0; g_sumsq[i] = 0.0; }
}
__global__ void deg_kernel(const int* __restrict__ dst) {
    int e = blockIdx.x * blockDim.x + threadIdx.x;
    if (e < EE) atomicAdd(&g_deg[dst[e]], 1);
}
__global__ void scan1_kernel() {   // 256 blocks x 256 thr
    __shared__ int sm[256];
    int b = blockIdx.x, t = threadIdx.x, i = b * 256 + t;
    int v = g_deg[i]; sm[t] = v; __syncthreads();
    for (int off = 1; off < 256; off <<= 1) {
        int x = (t >= off) ? sm[t - off] : 0;
        __syncthreads(); sm[t] += x; __syncthreads();
    }
    g_rowptr[i] = sm[t] - v;
    if (t == 255) g_bsum[b] = sm[t];
}
__global__ void scan2_kernel() {   // 1 block x 256
    __shared__ int sm[256];
    int t = threadIdx.x;
    int v = g_bsum[t]; sm[t] = v; __syncthreads();
    for (int off = 1; off < 256; off <<= 1) {
        int x = (t >= off) ? sm[t - off] : 0;
        __syncthreads(); sm[t] += x; __syncthreads();
    }
    g_bsum[t] = sm[t] - v;
}
__global__ void scan3_kernel() {
    int b = blockIdx.x, t = threadIdx.x, i = b * 256 + t;
    int r = g_rowptr[i] + g_bsum[b];
    g_rowptr[i] = r; g_cursor[i] = r;
    if (i == 0) g_rowptr[NN] = EE;
}
__global__ void fill_kernel(const int* __restrict__ src, const int* __restrict__ dst) {
    int e = blockIdx.x * blockDim.x + threadIdx.x;
    if (e < EE) {
        int p = atomicAdd(&g_cursor[dst[e]], 1);
        g_col[p] = src[e];
    }
}

// ---------------- z-GEMM: Z[i, half*64 + c] = concat[T(X[i]), pos[i]] @ W_half ----------------
// T(x) = relu(x*scale + shift) if scale != nullptr (folds BN+ReLU of previous stage).
// One warp per (node, half); lane owns 2 adjacent output channels (f32x2 packed).
__global__ void __launch_bounds__(256, 1) zgemm_kernel(
    const float* __restrict__ X, const float* __restrict__ pos,
    const float* __restrict__ Wa, const float* __restrict__ Wb,
    const float* __restrict__ scale, const float* __restrict__ shift,
    float* __restrict__ Z, int halves)
{
    __shared__ u64 dup[8][2][64];
    int warp = threadIdx.x >> 5, lane = threadIdx.x & 31;
    int gw = blockIdx.x * 8 + warp;
    int nw = gridDim.x * 8;
    int ntask = NN * halves;
    int Ct = halves << 6;
    bool hasT = (scale != nullptr);
    float s0 = 0.f, s1 = 0.f, t0 = 0.f, t1 = 0.f;
    if (hasT) { s0 = scale[2 * lane]; s1 = scale[2 * lane + 1];
                t0 = shift[2 * lane]; t1 = shift[2 * lane + 1]; }
    u64 Wreg[66];
    int curhalf = -1;
    int par = 0;
    for (int task = gw; task < ntask; task += nw) {
        int half = task >> 16;
        int node = task & (NN - 1);
        if (half != curhalf) {
            curhalf = half;
            const float* W = half ? Wb : Wa;
            #pragma unroll
            for (int k = 0; k < 66; k++)
                Wreg[k] = *(const u64*)(W + (size_t)k * 64 + 2 * lane);
        }
        float2 a = *(const float2*)(X + (size_t)node * 64 + 2 * lane);
        if (hasT) {
            a.x = fmaxf(fmaf(a.x, s0, t0), 0.f);
            a.y = fmaxf(fmaf(a.y, s1, t1), 0.f);
        }
        dup[warp][par][2 * lane]     = pk2(a.x, a.x);
        dup[warp][par][2 * lane + 1] = pk2(a.y, a.y);
        __syncwarp();
        u64 acc0 = 0ull, acc1 = 0ull, acc2 = 0ull, acc3 = 0ull;
        #pragma unroll
        for (int k = 0; k < 64; k += 4) {
            acc0 = f2fma(Wreg[k],     dup[warp][par][k],     acc0);
            acc1 = f2fma(Wreg[k + 1], dup[warp][par][k + 1], acc1);
            acc2 = f2fma(Wreg[k + 2], dup[warp][par][k + 2], acc2);
            acc3 = f2fma(Wreg[k + 3], dup[warp][par][k + 3], acc3);
        }
        float2 p = *(const float2*)(pos + (size_t)node * 2);
        acc0 = f2fma(Wreg[64], pk2(p.x, p.x), acc0);
        acc1 = f2fma(Wreg[65], pk2(p.y, p.y), acc1);
        u64 r = f2add(f2add(acc0, acc1), f2add(acc2, acc3));
        float rx, ry; upk2(r, rx, ry);
        float2 o; o.x = rx; o.y = ry;
        *(float2*)(Z + (size_t)node * Ct + (half << 6) + 2 * lane) = o;
        par ^= 1;
    }
}

// ---------------- segment max (includes implicit self-loop), subtracts pos_i @ Wl_pos ----------------
__global__ void segmax_kernel(
    const float* __restrict__ Z, const float* __restrict__ pos,
    const float* __restrict__ Wa, const float* __restrict__ Wb,
    float* __restrict__ M, int halves)
{
    int gw = (blockIdx.x * blockDim.x + threadIdx.x) >> 5;
    int lane = threadIdx.x & 31;
    int nw = (gridDim.x * blockDim.x) >> 5;
    int ntask = NN * halves;
    int Ct = halves << 6;
    for (int task = gw; task < ntask; task += nw) {
        int half = task >> 16;
        int node = task & (NN - 1);
        int coff = (half << 6) + 2 * lane;
        const float* zr = Z + coff;
        float2 m = *(const float2*)(zr + (size_t)node * Ct);   // self-loop
        int beg = g_rowptr[node], end = g_rowptr[node + 1];
        int j = beg;
        for (; j + 4 <= end; j += 4) {
            int i0 = g_col[j], i1 = g_col[j + 1], i2 = g_col[j + 2], i3 = g_col[j + 3];
            float2 v0 = *(const float2*)(zr + (size_t)i0 * Ct);
            float2 v1 = *(const float2*)(zr + (size_t)i1 * Ct);
            float2 v2 = *(const float2*)(zr + (size_t)i2 * Ct);
            float2 v3 = *(const float2*)(zr + (size_t)i3 * Ct);
            m.x = fmaxf(m.x, fmaxf(fmaxf(v0.x, v1.x), fmaxf(v2.x, v3.x)));
            m.y = fmaxf(m.y, fmaxf(fmaxf(v0.y, v1.y), fmaxf(v2.y, v3.y)));
        }
        for (; j < end; j++) {
            int s = g_col[j];
            float2 v = *(const float2*)(zr + (size_t)s * Ct);
            m.x = fmaxf(m.x, v.x); m.y = fmaxf(m.y, v.y);
        }
        const float* W = half ? Wb : Wa;
        float2 w0 = *(const float2*)(W + 64 * 64 + 2 * lane);
        float2 w1 = *(const float2*)(W + 65 * 64 + 2 * lane);
        float2 p = *(const float2*)(pos + (size_t)node * 2);
        m.x -= p.x * w0.x + p.y * w1.x;
        m.y -= p.x * w0.y + p.y * w1.y;
        *(float2*)(M + (size_t)node * Ct + coff) = m;
    }
}

// ---------------- m-GEMM: OUT[i, c] = M[i, inoff:inoff+64] @ W (+bias), optional BN stats ----------------
__global__ void __launch_bounds__(256, 1) mgemm_kernel(
    const float* __restrict__ M, int Cin, int inoff,
    const float* __restrict__ W, int COUT,
    const float* __restrict__ bias,
    float* __restrict__ OUT, int ostride,
    int stats_off, int halves)
{
    __shared__ u64 dup[8][2][64];
    int warp = threadIdx.x >> 5, lane = threadIdx.x & 31;
    int gw = blockIdx.x * 8 + warp;
    int nw = gridDim.x * 8;
    int ntask = NN * halves;
    u64 Wreg[64];
    int curhalf = -1;
    int c0 = 0; bool v0 = false, v1 = false;
    float bx = 0.f, by = 0.f;
    float lsum0 = 0.f, lsq0 = 0.f, lsum1 = 0.f, lsq1 = 0.f;
    int par = 0;
    for (int task = gw; task < ntask; task += nw) {
        int half = task >> 16;
        int node = task & (NN - 1);
        if (half != curhalf) {
            curhalf = half;
            c0 = (half << 6) + 2 * lane;
            v0 = (c0 < COUT); v1 = (c0 + 1 < COUT);
            #pragma unroll
            for (int k = 0; k < 64; k++) {
                float wx = v0 ? W[(size_t)k * COUT + c0] : 0.f;
                float wy = v1 ? W[(size_t)k * COUT + c0 + 1] : 0.f;
                Wreg[k] = pk2(wx, wy);
            }
            bx = (bias && v0) ? bias[c0] : 0.f;
            by = (bias && v1) ? bias[c0 + 1] : 0.f;
        }
        float2 a = *(const float2*)(M + (size_t)node * Cin + inoff + 2 * lane);
        dup[warp][par][2 * lane]     = pk2(a.x, a.x);
        dup[warp][par][2 * lane + 1] = pk2(a.y, a.y);
        __syncwarp();
        u64 acc0 = 0ull, acc1 = 0ull, acc2 = 0ull, acc3 = 0ull;
        #pragma unroll
        for (int k = 0; k < 64; k += 4) {
            acc0 = f2fma(Wreg[k],     dup[warp][par][k],     acc0);
            acc1 = f2fma(Wreg[k + 1], dup[warp][par][k + 1], acc1);
            acc2 = f2fma(Wreg[k + 2], dup[warp][par][k + 2], acc2);
            acc3 = f2fma(Wreg[k + 3], dup[warp][par][k + 3], acc3);
        }
        u64 r = f2add(f2add(acc0, acc1), f2add(acc2, acc3));
        float rx, ry; upk2(r, rx, ry);
        rx += bx; ry += by;
        if (stats_off >= 0) {
            lsum0 += rx; lsq0 += rx * rx;
            lsum1 += ry; lsq1 += ry * ry;
        }
        if (v0) OUT[(size_t)node * ostride + c0] = rx;
        if (v1) OUT[(size_t)node * ostride + c0 + 1] = ry;
        par ^= 1;
    }
    if (stats_off >= 0) {
        atomicAdd(&g_sum[stats_off + 2 * lane],     (double)lsum0);
        atomicAdd(&g_sum[stats_off + 2 * lane + 1], (double)lsum1);
        atomicAdd(&g_sumsq[stats_off + 2 * lane],     (double)lsq0);
        atomicAdd(&g_sumsq[stats_off + 2 * lane + 1], (double)lsq1);
    }
}

// ---------------- tiny-output heads (COUT <= 4), thread per node ----------------
template <int COUT>
__global__ void head_kernel(const float* __restrict__ M, int Cin, int inoff,
                            const float* __restrict__ W, const float* __restrict__ bias,
                            float* __restrict__ OUT, int ostride)
{
    __shared__ float Ws[64 * COUT];
    for (int i = threadIdx.x; i < 64 * COUT; i += blockDim.x) Ws[i] = W[i];
    __syncthreads();
    int node = blockIdx.x * blockDim.x + threadIdx.x;
    if (node >= NN) return;
    float acc[COUT];
    #pragma unroll
    for (int c = 0; c < COUT; c++) acc[c] = bias[c];
    const float* a = M + (size_t)node * Cin + inoff;
    #pragma unroll 8
    for (int k = 0; k < 64; k++) {
        float av = a[k];
        #pragma unroll
        for (int c = 0; c < COUT; c++) acc[c] = fmaf(av, Ws[k * COUT + c], acc[c]);
    }
    #pragma unroll
    for (int c = 0; c < COUT; c++) OUT[(size_t)node * ostride + c] = acc[c];
}

// ---------------- BN finalize: scale/shift per channel ----------------
__global__ void bnfin_kernel(const float* __restrict__ g0, const float* __restrict__ b0,
                             const float* __restrict__ g1, const float* __restrict__ b1,
                             int nch, int off)
{
    int t = threadIdx.x;
    if (t >= nch) return;
    double mean = g_sum[off + t] / (double)NN;
    double var  = g_sumsq[off + t] / (double)NN - mean * mean;
    float gm = (t < 64) ? g0[t] : g1[t - 64];
    float bt = (t < 64) ? b0[t] : b1[t - 64];
    float s = gm * rsqrtf((float)var + BNEPS);
    g_s[off + t] = s;
    g_t[off + t] = bt - (float)mean * s;
}

// ---------------- host orchestration ----------------
static void* symaddr(const void* symbol) {
    void* p = nullptr;
    cudaGetSymbolAddress(&p, symbol);
    return p;
}

extern "C" void kernel_launch(void* const* d_in, const int* in_sizes, int n_in,
                              void* d_out, int out_size)
{
    const float* x   = (const float*)d_in[0];
    const float* pos = (const float*)d_in[1];
    const int*   ei  = (const int*)d_in[2];
    const float* W11 = (const float*)d_in[3];  const float* W12 = (const float*)d_in[4];
    const float* g1  = (const float*)d_in[5];  const float* b1  = (const float*)d_in[6];
    const float* W21 = (const float*)d_in[7];  const float* W22 = (const float*)d_in[8];
    const float* g2  = (const float*)d_in[9];  const float* b2  = (const float*)d_in[10];
    const float* W31 = (const float*)d_in[11]; const float* W32 = (const float*)d_in[12];
    const float* g3  = (const float*)d_in[13]; const float* b3  = (const float*)d_in[14];
    const float* Wr1 = (const float*)d_in[15]; const float* Wr2 = (const float*)d_in[16];
    const float* br2 = (const float*)d_in[17];
    const float* Wc1 = (const float*)d_in[18]; const float* Wc2 = (const float*)d_in[19];
    const float* bc2 = (const float*)d_in[20];
    const float* Wo1 = (const float*)d_in[21]; const float* Wo2 = (const float*)d_in[22];
    const float* bo2 = (const float*)d_in[23];
    float* out = (float*)d_out;

    const int* src = ei;
    const int* dst = ei + EE;

    float* Z   = (float*)symaddr(g_z);
    float* M   = (float*)symaddr(g_m);
    float* H1  = (float*)symaddr(g_h1);
    float* H2  = (float*)symaddr(g_h2);
    float* H3  = (float*)symaddr(g_h3);
    float* Sv  = (float*)symaddr(g_s);
    float* Tv  = (float*)symaddr(g_t);

    const int GB = 296;  // grid-stride blocks for GEMM kernels (reg-limited, ~1 block/SM)

    // ---- CSR (built each launch; deterministic result) ----
    zero_kernel<<<NN / 256, 256>>>();
    deg_kernel<<<EE / 256, 256>>>(dst);
    scan1_kernel<<<256, 256>>>();
    scan2_kernel<<<1, 256>>>();
    scan3_kernel<<<256, 256>>>();
    fill_kernel<<<EE / 256, 256>>>(src, dst);

    // ---- conv1: x -> h1 ----
    zgemm_kernel<<<GB, 256>>>(x, pos, W11, nullptr, nullptr, nullptr, Z, 1);
    segmax_kernel<<<NN / 8, 256>>>(Z, pos, W11, nullptr, M, 1);
    mgemm_kernel<<<GB, 256>>>(M, 64, 0, W12, 64, nullptr, H1, 64, 0, 1);
    bnfin_kernel<<<1, 64>>>(g1, b1, g1, b1, 64, 0);

    // ---- conv2 + conv3 fused: x1 = relu(bn1(h1)) -> h2, h3 ----
    zgemm_kernel<<<GB, 256>>>(H1, pos, W21, W31, Sv + 0, Tv + 0, Z, 2);
    segmax_kernel<<<NN * 2 / 8, 256>>>(Z, pos, W21, W31, M, 2);
    mgemm_kernel<<<GB, 256>>>(M, 128, 0,  W22, 64, nullptr, H2, 64, 64, 1);
    mgemm_kernel<<<GB, 256>>>(M, 128, 64, W32, 64, nullptr, H3, 64, 128, 1);
    bnfin_kernel<<<1, 128>>>(g2, b2, g3, b3, 128, 64);

    // ---- reg head: x2 = relu(bn2(h2)) -> out[N*101 .. N*101+4N) ----
    zgemm_kernel<<<GB, 256>>>(H2, pos, Wr1, nullptr, Sv + 64, Tv + 64, Z, 1);
    segmax_kernel<<<NN / 8, 256>>>(Z, pos, Wr1, nullptr, M, 1);
    head_kernel<4><<<NN / 256, 256>>>(M, 64, 0, Wr2, br2, out + (size_t)NN * CC, 4);

    // ---- cls + obj heads fused: x3 = relu(bn3(h3)) ----
    zgemm_kernel<<<GB, 256>>>(H3, pos, Wc1, Wo1, Sv + 128, Tv + 128, Z, 2);
    segmax_kernel<<<NN * 2 / 8, 256>>>(Z, pos, Wc1, Wo1, M, 2);
    mgemm_kernel<<<GB, 256>>>(M, 128, 0, Wc2, CC, bc2, out, CC, -1, 2);
    head_kernel<1><<<NN / 256, 256>>>(M, 128, 64, Wo2, bo2, out + (size_t)NN * (CC + 4), 1);

    (void)in_sizes; (void)n_in; (void)out_size;
}